// round 13
// baseline (speedup 1.0000x reference)
#include <cuda_runtime.h>
#include <cuda_bf16.h>
#include <cuda_fp16.h>
#include <math.h>
#include <stdint.h>

#define N0C 30000
#define N1C 90000
#define N2C 60000
#define NTOT (N0C + N1C + N2C)   // 180000
#define DIN  256
#define DOUT 128
#define HEADS 4
#define EMAX 1320000

#define TILEB  8192u             // 128 rows x 32 fp16 (64B) = 8KB
#define STAGEB (3u * TILEB)      // A, Bhi, Blo
#define NSTG   3u
#define GSMEM  (NSTG * STAGEB + 1024u)

// ---------------- scratch (device globals; no runtime allocation) ------------
__device__ __align__(128) __half g_Xf16[(size_t)NTOT * DIN];
__device__ __align__(128) __half g_W1t_hi[HEADS * DOUT * DIN];    // [h][n][k]
__device__ __align__(128) __half g_W1t_lo[HEADS * DOUT * DIN];
__device__ __align__(128) __half g_Waggt_hi[HEADS * DOUT * 512];  // [h][n][k]
__device__ __align__(128) __half g_Waggt_lo[HEADS * DOUT * 512];
__device__ __align__(128) __half g_Yf16[(size_t)NTOT * HEADS * DOUT]; // [row][h][128]
__device__ __align__(128) float  g_a1 [N0C * HEADS];    // [node][h]
__device__ __align__(128) float  g_a2 [NTOT * HEADS];   // [node][h]
__device__ __align__(128) __half g_aggf16[(size_t)HEADS * 3 * N0C * DOUT]; // [h][lvl][row][128]
// CSR scratch
__device__ int g_cnt   [3 * N0C];
__device__ int g_rowptr[3 * (N0C + 1)];
__device__ int g_pos   [3 * N0C];
__device__ int g_ecol  [EMAX];

// ---------------- PTX helpers (all base-ISA) ----------------------------------
__device__ __forceinline__ uint32_t smem_u32(const void* p) {
    uint32_t a;
    asm("{ .reg .u64 t; cvta.to.shared.u64 t, %1; cvt.u32.u64 %0, t; }" : "=r"(a) : "l"(p));
    return a;
}
__device__ __forceinline__ void cpa16(uint32_t dst, const void* src, uint32_t n) {
    asm volatile("cp.async.cg.shared.global [%0], [%1], 16, %2;" :: "r"(dst), "l"(src), "r"(n));
}
__device__ __forceinline__ void cp_commit() { asm volatile("cp.async.commit_group;" ::: "memory"); }
__device__ __forceinline__ void cpwait2()  { asm volatile("cp.async.wait_group 2;" ::: "memory"); }
__device__ __forceinline__ void cpwait1()  { asm volatile("cp.async.wait_group 1;" ::: "memory"); }
__device__ __forceinline__ void cpwait0()  { asm volatile("cp.async.wait_group 0;" ::: "memory"); }

__device__ __forceinline__ void ldsm4(uint32_t* r, uint32_t addr) {
    asm volatile("ldmatrix.sync.aligned.m8n8.x4.shared.b16 {%0,%1,%2,%3}, [%4];"
                 : "=r"(r[0]), "=r"(r[1]), "=r"(r[2]), "=r"(r[3]) : "r"(addr));
}
__device__ __forceinline__ void mma16816h(float* c, const uint32_t* a, const uint32_t* b) {
    asm volatile("mma.sync.aligned.m16n8k16.row.col.f32.f16.f16.f32 "
                 "{%0,%1,%2,%3}, {%4,%5,%6,%7}, {%8,%9}, {%0,%1,%2,%3};"
                 : "+f"(c[0]), "+f"(c[1]), "+f"(c[2]), "+f"(c[3])
                 : "r"(a[0]), "r"(a[1]), "r"(a[2]), "r"(a[3]), "r"(b[0]), "r"(b[1]));
}
__device__ __forceinline__ uint32_t swz(uint32_t r, uint32_t c) {
    return r * 64u + ((c ^ ((r >> 1) & 3u)) << 4);
}

// ---------------- pack helpers ------------------------------------------------
__device__ __forceinline__ uint32_t pack2h(__half a, __half b) {
    return (uint32_t)__half_as_ushort(a) | ((uint32_t)__half_as_ushort(b) << 16);
}
__device__ __forceinline__ void split1h(float v, __half& h, __half& l) {
    h = __float2half_rn(v);
    l = __float2half_rn(v - __half2float(h));
}

__global__ __launch_bounds__(256) void pack_x_kernel(
    const float* __restrict__ x0, const float* __restrict__ x1, const float* __restrict__ x2)
{
    size_t i = (size_t)blockIdx.x * 256 + threadIdx.x;   // float4 index
    if (i >= (size_t)NTOT * (DIN / 4)) return;
    int row = (int)(i >> 6);
    int c4  = (int)(i & 63);
    const float* src;
    if (row < N0C)            src = x0 + (size_t)row * DIN;
    else if (row < N0C + N1C) src = x1 + (size_t)(row - N0C) * DIN;
    else                      src = x2 + (size_t)(row - N0C - N1C) * DIN;
    float4 v = reinterpret_cast<const float4*>(src)[c4];
    reinterpret_cast<uint2*>(g_Xf16)[i] = make_uint2(
        pack2h(__float2half_rn(v.x), __float2half_rn(v.y)),
        pack2h(__float2half_rn(v.z), __float2half_rn(v.w)));
}

__global__ __launch_bounds__(256) void split_w1_kernel(const float* __restrict__ W1)
{
    int i = blockIdx.x * 256 + threadIdx.x;              // [h][n][k]
    if (i >= HEADS * DOUT * DIN) return;
    int h = i >> 15, n = (i >> 8) & 127, k = i & 255;
    float v = W1[(size_t)h * DIN * DOUT + (size_t)k * DOUT + n];
    __half hi, lo; split1h(v, hi, lo);
    g_W1t_hi[i] = hi; g_W1t_lo[i] = lo;
}

__global__ __launch_bounds__(256) void split_wagg_kernel(const float* __restrict__ Wagg)
{
    int i = blockIdx.x * 256 + threadIdx.x;              // [h][n][k], k<512
    if (i >= HEADS * DOUT * 512) return;
    int h = i >> 16, n = (i >> 9) & 127, k = i & 511;
    float v = Wagg[(size_t)h * 512 * DOUT + (size_t)k * DOUT + n];
    __half hi, lo; split1h(v, hi, lo);
    g_Waggt_hi[i] = hi; g_Waggt_lo[i] = lo;
}

__global__ __launch_bounds__(256) void zero_small_kernel()
{
    int i = blockIdx.x * 256 + threadIdx.x;
    if (i < N0C * HEADS)  g_a1[i] = 0.f;
    if (i < NTOT * HEADS) g_a2[i] = 0.f;
    if (i < 3 * N0C)      g_cnt[i] = 0;
}

// ---------------- CSR build ----------------------------------------------------
__global__ __launch_bounds__(256) void hist_kernel(const int* __restrict__ rows, int nnz, int lvl)
{
    int i = blockIdx.x * 256 + threadIdx.x;
    if (i < nnz) atomicAdd(&g_cnt[lvl * N0C + rows[i]], 1);
}

__global__ __launch_bounds__(1024) void scan_kernel()   // grid = 3
{
    const int lvl = blockIdx.x;
    const int* cnt = g_cnt + lvl * N0C;
    int* rp  = g_rowptr + lvl * (N0C + 1);
    int* pos = g_pos + lvl * N0C;
    __shared__ int ssum[1024];
    const int CH = (N0C + 1023) / 1024;   // 30
    int t = threadIdx.x;
    int base = t * CH;
    int s = 0;
    for (int k = 0; k < CH; k++) { int idx = base + k; if (idx < N0C) s += cnt[idx]; }
    ssum[t] = s; __syncthreads();
    for (int off = 1; off < 1024; off <<= 1) {
        int v = (t >= off) ? ssum[t - off] : 0;
        __syncthreads();
        ssum[t] += v;
        __syncthreads();
    }
    int run = (t == 0) ? 0 : ssum[t - 1];
    for (int k = 0; k < CH; k++) {
        int idx = base + k;
        if (idx < N0C) { rp[idx] = run; pos[idx] = run; run += cnt[idx]; }
    }
    if (t == 1023) rp[N0C] = run;
}

__global__ __launch_bounds__(256) void scatter_kernel(
    const int* __restrict__ rows, const int* __restrict__ cols,
    int nnz, int lvl, int ebase)
{
    int i = blockIdx.x * 256 + threadIdx.x;
    if (i >= nnz) return;
    int p = atomicAdd(&g_pos[lvl * N0C + rows[i]], 1);
    g_ecol[ebase + p] = cols[i];
}

// ---------------- 2-pass MMA compute core --------------------------------------
__device__ __forceinline__ void compute_stage2(uint32_t s0, int mwarp, int nwarp,
                                               int lane, float c[2][8][4])
{
    uint32_t a[2][2][4];
#pragma unroll
    for (int i = 0; i < 2; i++)
#pragma unroll
        for (int kk = 0; kk < 2; kk++) {
            uint32_t off = swz((uint32_t)(mwarp + i * 16 + (lane & 15)),
                               (uint32_t)(kk * 2 + (lane >> 4)));
            ldsm4(a[i][kk], s0 + off);
        }
#pragma unroll
    for (int j = 0; j < 4; j++) {
        uint32_t nrow = (uint32_t)(nwarp + j * 16 + ((lane >> 4) << 3) + (lane & 7));
        uint32_t csel = (uint32_t)((lane >> 3) & 1);
#pragma unroll
        for (int kk = 0; kk < 2; kk++) {
            uint32_t off = swz(nrow, (uint32_t)(kk * 2) + csel);
            uint32_t bh[4], bl[4];
            ldsm4(bh, s0 + TILEB + off);
            ldsm4(bl, s0 + 2 * TILEB + off);
#pragma unroll
            for (int i = 0; i < 2; i++) {
                mma16816h(c[i][j * 2 + 0], a[i][kk], bh);
                mma16816h(c[i][j * 2 + 1], a[i][kk], bh + 2);
                mma16816h(c[i][j * 2 + 0], a[i][kk], bl);
                mma16816h(c[i][j * 2 + 1], a[i][kk], bl + 2);
            }
        }
    }
}

// ---------------- GEMM1: Y = relu(X@W1[h]+b1[h]) + fused a1/a2 partial dots ----
// grid = (HEADS, tiles); occ 2 CTAs/SM; 3-stage cp.async pipeline.
__global__ __launch_bounds__(256, 2) void gemm1_mma(
    const float* __restrict__ b1, const float* __restrict__ a1w,
    const float* __restrict__ a2w)
{
    extern __shared__ char smem[];
    __shared__ float sBias[128], sA1w[128], sA2w[128];
    uint32_t sb = smem_u32(smem);
    uint32_t tb = (sb + 1023u) & ~1023u;
    const int tid = threadIdx.x, lane = tid & 31, wid = tid >> 5;
    const int h = blockIdx.x, m0 = blockIdx.y * 128;
    const int mwarp = (wid & 3) * 32, nwarp = (wid >> 2) * 64;

    if (tid < 128) {
        sBias[tid] = b1[h * DOUT + tid];
        sA1w[tid]  = a1w[h * DOUT + tid];
        sA2w[tid]  = a2w[h * DOUT + tid];
    }

    float c[2][8][4];
#pragma unroll
    for (int i = 0; i < 2; i++)
#pragma unroll
        for (int j = 0; j < 8; j++)
#pragma unroll
            for (int q = 0; q < 4; q++) c[i][j][q] = 0.f;

    auto load = [&](int stage, int ks) {
        uint32_t s0 = tb + (uint32_t)stage * STAGEB;
        int k0 = ks * 32;
#pragma unroll
        for (int t = 0; t < 2; t++) {
            int idx = tid * 2 + t;
            int r = idx >> 2, cc = idx & 3;
            uint32_t dsw = swz((uint32_t)r, (uint32_t)cc);
            uint32_t n = (m0 + r < NTOT) ? 16u : 0u;
            size_t aoff = (size_t)(m0 + r) * DIN + k0 + cc * 8;
            size_t boff = ((size_t)h * DOUT + r) * DIN + k0 + cc * 8;
            cpa16(s0 + dsw,             g_Xf16   + aoff, n);
            cpa16(s0 + TILEB + dsw,     g_W1t_hi + boff, 16u);
            cpa16(s0 + 2 * TILEB + dsw, g_W1t_lo + boff, 16u);
        }
        cp_commit();
    };

    const int NKS = DIN / 32;   // 8
    load(0, 0);
    load(1, 1);
    for (int ks = 0; ks < NKS; ks++) {
        if (ks + 2 < NKS) { load((ks + 2) % 3, ks + 2); cpwait2(); }
        else if (ks + 1 < NKS) { cpwait1(); }
        else { cpwait0(); }
        __syncthreads();
        compute_stage2(tb + (uint32_t)(ks % 3) * STAGEB, mwarp, nwarp, lane, c);
        __syncthreads();
    }

    // epilogue: Yf16 [row][h][128]; fused a1/a2 dots (head-interleaved)
#pragma unroll
    for (int i = 0; i < 2; i++) {
        int r0 = m0 + mwarp + i * 16 + (lane >> 2);
#pragma unroll
        for (int v = 0; v < 2; v++) {
            int row = r0 + v * 8;
            if (row >= NTOT) continue;
            size_t yfb = ((size_t)row * HEADS + h) * DOUT;
            float p1 = 0.f, p2 = 0.f;
#pragma unroll
            for (int j = 0; j < 8; j++) {
                int col = nwarp + j * 8 + (lane & 3) * 2;
                float y0 = fmaxf(c[i][j][v * 2 + 0] + sBias[col], 0.f);
                float y1 = fmaxf(c[i][j][v * 2 + 1] + sBias[col + 1], 0.f);
                p1 = fmaf(y0, sA1w[col], p1); p1 = fmaf(y1, sA1w[col + 1], p1);
                p2 = fmaf(y0, sA2w[col], p2); p2 = fmaf(y1, sA2w[col + 1], p2);
                *reinterpret_cast<uint32_t*>(g_Yf16 + yfb + col) =
                    pack2h(__float2half_rn(y0), __float2half_rn(y1));
            }
            atomicAdd(&g_a2[row * HEADS + h], p2);
            if (row < N0C) atomicAdd(&g_a1[row * HEADS + h], p1);
        }
    }
}

// ---------------- edge aggregation: all 4 heads per warp, 4-edge unroll ---------
__global__ __launch_bounds__(256) void edge_agg_kernel(
    const float* __restrict__ a1b, const float* __restrict__ a2b,
    int ebase1, int ebase2)
{
    int w = blockIdx.x * 8 + (threadIdx.x >> 5);
    if (w >= N0C * 3) return;
    const int lane = threadIdx.x & 31;
    int lvl = w / N0C;
    int row = w - lvl * N0C;

    int coff, eb;
    if (lvl == 0)      { coff = 0;          eb = 0; }
    else if (lvl == 1) { coff = N0C;        eb = ebase1; }
    else               { coff = N0C + N1C;  eb = ebase2; }

    int beg = g_rowptr[lvl * (N0C + 1) + row];
    int end = g_rowptr[lvl * (N0C + 1) + row + 1];

    float4 a1v = *reinterpret_cast<const float4*>(g_a1 + row * HEADS);
    float a1r[4];
#pragma unroll
    for (int h = 0; h < 4; h++)
        a1r[h] = ((const float*)&a1v)[h] + a1b[h] + a2b[h];

    const float* a2t = g_a2 + (size_t)coff * HEADS;
    const __half* yh = g_Yf16 + (size_t)coff * HEADS * DOUT;
    const int* ec = g_ecol + eb;

    float acc[4][4];
#pragma unroll
    for (int h = 0; h < 4; h++)
#pragma unroll
        for (int q = 0; q < 4; q++) acc[h][q] = 0.f;

    int e = beg;
    for (; e + 3 < end; e += 4) {
        int cidx[4];
#pragma unroll
        for (int k = 0; k < 4; k++) cidx[k] = __ldg(ec + e + k);
        float4 a2e[4];
#pragma unroll
        for (int k = 0; k < 4; k++)
            a2e[k] = *reinterpret_cast<const float4*>(a2t + (size_t)cidx[k] * HEADS);
        uint2 u[4][4];
#pragma unroll
        for (int k = 0; k < 4; k++)
#pragma unroll
            for (int h = 0; h < 4; h++)
                u[k][h] = *reinterpret_cast<const uint2*>(
                    yh + ((size_t)cidx[k] * HEADS + h) * DOUT + lane * 4);
#pragma unroll
        for (int k = 0; k < 4; k++)
#pragma unroll
            for (int h = 0; h < 4; h++) {
                float att = __fdividef(1.f, 1.f + __expf(-(a1r[h] + ((const float*)&a2e[k])[h])));
                float2 f0 = __half22float2(*reinterpret_cast<__half2*>(&u[k][h].x));
                float2 f1 = __half22float2(*reinterpret_cast<__half2*>(&u[k][h].y));
                acc[h][0] = fmaf(att, f0.x, acc[h][0]); acc[h][1] = fmaf(att, f0.y, acc[h][1]);
                acc[h][2] = fmaf(att, f1.x, acc[h][2]); acc[h][3] = fmaf(att, f1.y, acc[h][3]);
            }
    }
    for (; e < end; e++) {
        int c0 = __ldg(ec + e);
        float4 a20 = *reinterpret_cast<const float4*>(a2t + (size_t)c0 * HEADS);
        uint2 u0[4];
#pragma unroll
        for (int h = 0; h < 4; h++)
            u0[h] = *reinterpret_cast<const uint2*>(yh + ((size_t)c0 * HEADS + h) * DOUT + lane * 4);
#pragma unroll
        for (int h = 0; h < 4; h++) {
            float att0 = __fdividef(1.f, 1.f + __expf(-(a1r[h] + ((const float*)&a20)[h])));
            float2 f0 = __half22float2(*reinterpret_cast<__half2*>(&u0[h].x));
            float2 f1 = __half22float2(*reinterpret_cast<__half2*>(&u0[h].y));
            acc[h][0] = fmaf(att0, f0.x, acc[h][0]); acc[h][1] = fmaf(att0, f0.y, acc[h][1]);
            acc[h][2] = fmaf(att0, f1.x, acc[h][2]); acc[h][3] = fmaf(att0, f1.y, acc[h][3]);
        }
    }

#pragma unroll
    for (int h = 0; h < 4; h++) {
        size_t ob = (((size_t)h * 3 + lvl) * N0C + row) * DOUT + lane * 4;
        *reinterpret_cast<uint2*>(g_aggf16 + ob) = make_uint2(
            pack2h(__float2half_rn(acc[h][0]), __float2half_rn(acc[h][1])),
            pack2h(__float2half_rn(acc[h][2]), __float2half_rn(acc[h][3])));
    }
}

// ---------------- GEMM2: out = mean_h(cat_h @ Wagg[h]) + mean bias --------------
__global__ __launch_bounds__(256, 2) void gemm2_mma(
    const float* __restrict__ bagg, float* __restrict__ out)
{
    extern __shared__ char smem[];
    __shared__ float sBsum[128];
    uint32_t sb = smem_u32(smem);
    uint32_t tb = (sb + 1023u) & ~1023u;
    const int tid = threadIdx.x, lane = tid & 31, wid = tid >> 5;
    const int m0 = blockIdx.x * 128;
    const int mwarp = (wid & 3) * 32, nwarp = (wid >> 2) * 64;

    if (tid < 128)
        sBsum[tid] = bagg[tid] + bagg[128 + tid] + bagg[256 + tid] + bagg[384 + tid];

    float c[2][8][4];
#pragma unroll
    for (int i = 0; i < 2; i++)
#pragma unroll
        for (int j = 0; j < 8; j++)
#pragma unroll
            for (int q = 0; q < 4; q++) c[i][j][q] = 0.f;

    auto load = [&](int stage, int ks) {
        uint32_t s0 = tb + (uint32_t)stage * STAGEB;
        int chunk = ks >> 2, inner = ks & 3;
        int h = chunk >> 2, part = chunk & 3;
        size_t bbase = ((size_t)h * DOUT) * 512 + part * 128;
#pragma unroll
        for (int t = 0; t < 2; t++) {
            int idx = tid * 2 + t;
            int r = idx >> 2, cc = idx & 3;
            uint32_t dsw = swz((uint32_t)r, (uint32_t)cc);
            uint32_t n = (m0 + r < N0C) ? 16u : 0u;
            size_t aoff;
            const __half* asrc;
            if (part == 0) {
                asrc = g_Yf16;
                aoff = ((size_t)(m0 + r) * HEADS + h) * DOUT + inner * 32 + cc * 8;
            } else {
                asrc = g_aggf16;
                aoff = ((size_t)(h * 3 + part - 1) * N0C + m0 + r) * DOUT + inner * 32 + cc * 8;
            }
            size_t boff = bbase + (size_t)r * 512 + inner * 32 + cc * 8;
            cpa16(s0 + dsw,             asrc + aoff, n);
            cpa16(s0 + TILEB + dsw,     g_Waggt_hi + boff, 16u);
            cpa16(s0 + 2 * TILEB + dsw, g_Waggt_lo + boff, 16u);
        }
        cp_commit();
    };

    const int NKS = 64;   // 4 heads * 4 parts * 4 inner
    load(0, 0);
    load(1, 1);
    for (int ks = 0; ks < NKS; ks++) {
        if (ks + 2 < NKS) { load((ks + 2) % 3, ks + 2); cpwait2(); }
        else if (ks + 1 < NKS) { cpwait1(); }
        else { cpwait0(); }
        __syncthreads();
        compute_stage2(tb + (uint32_t)(ks % 3) * STAGEB, mwarp, nwarp, lane, c);
        __syncthreads();
    }

#pragma unroll
    for (int i = 0; i < 2; i++) {
        int r0 = m0 + mwarp + i * 16 + (lane >> 2);
#pragma unroll
        for (int v = 0; v < 2; v++) {
            int row = r0 + v * 8;
            if (row >= N0C) continue;
            float* dst = out + (size_t)row * DOUT;
#pragma unroll
            for (int j = 0; j < 8; j++) {
                int col = nwarp + j * 8 + (lane & 3) * 2;
                float v0 = 0.25f * (c[i][j][v * 2 + 0] + sBsum[col]);
                float v1 = 0.25f * (c[i][j][v * 2 + 1] + sBsum[col + 1]);
                *reinterpret_cast<float2*>(dst + col) = make_float2(v0, v1);
            }
        }
    }
}

// ---------------- launcher -------------------------------------------------------
extern "C" void kernel_launch(void* const* d_in, const int* in_sizes, int n_in,
                              void* d_out, int out_size)
{
    const float* x0    = (const float*)d_in[0];
    const float* x1    = (const float*)d_in[1];
    const float* x2    = (const float*)d_in[2];
    const int*   rows0 = (const int*)  d_in[3];
    const int*   cols0 = (const int*)  d_in[4];
    const int*   rows1 = (const int*)  d_in[5];
    const int*   cols1 = (const int*)  d_in[6];
    const int*   rows2 = (const int*)  d_in[7];
    const int*   cols2 = (const int*)  d_in[8];
    const float* W1    = (const float*)d_in[9];
    const float* b1    = (const float*)d_in[10];
    const float* a1w   = (const float*)d_in[11];
    const float* a1b   = (const float*)d_in[12];
    const float* a2w   = (const float*)d_in[13];
    const float* a2b   = (const float*)d_in[14];
    const float* Wagg  = (const float*)d_in[15];
    const float* bagg  = (const float*)d_in[16];
    float* out = (float*)d_out;

    const int nnz0 = in_sizes[3];
    const int nnz1 = in_sizes[5];
    const int nnz2 = in_sizes[7];

    static bool init_done = false;
    static cudaStream_t s2;
    static cudaEvent_t evFork, evCSR;
    if (!init_done) {
        cudaFuncSetAttribute(gemm1_mma, cudaFuncAttributeMaxDynamicSharedMemorySize, GSMEM);
        cudaFuncSetAttribute(gemm2_mma, cudaFuncAttributeMaxDynamicSharedMemorySize, GSMEM);
        cudaStreamCreateWithFlags(&s2, cudaStreamNonBlocking);
        cudaEventCreateWithFlags(&evFork, cudaEventDisableTiming);
        cudaEventCreateWithFlags(&evCSR, cudaEventDisableTiming);
        init_done = true;
    }

    // 0) zero (feeds both branches)
    zero_small_kernel<<<(NTOT * HEADS + 255) / 256, 256>>>();

    // fork: CSR build on side stream, concurrent with pack/split/gemm1
    cudaEventRecord(evFork, 0);
    cudaStreamWaitEvent(s2, evFork, 0);
    hist_kernel<<<(nnz0 + 255) / 256, 256, 0, s2>>>(rows0, nnz0, 0);
    hist_kernel<<<(nnz1 + 255) / 256, 256, 0, s2>>>(rows1, nnz1, 1);
    hist_kernel<<<(nnz2 + 255) / 256, 256, 0, s2>>>(rows2, nnz2, 2);
    scan_kernel<<<3, 1024, 0, s2>>>();
    scatter_kernel<<<(nnz0 + 255) / 256, 256, 0, s2>>>(rows0, cols0, nnz0, 0, 0);
    scatter_kernel<<<(nnz1 + 255) / 256, 256, 0, s2>>>(rows1, cols1, nnz1, 1, nnz0);
    scatter_kernel<<<(nnz2 + 255) / 256, 256, 0, s2>>>(rows2, cols2, nnz2, 2, nnz0 + nnz1);
    cudaEventRecord(evCSR, s2);

    // main branch: pack inputs, gemm1 (single launch, all heads)
    pack_x_kernel<<<(NTOT * (DIN / 4) + 255) / 256, 256>>>(x0, x1, x2);
    split_w1_kernel<<<(HEADS * DOUT * DIN + 255) / 256, 256>>>(W1);
    split_wagg_kernel<<<(HEADS * DOUT * 512 + 255) / 256, 256>>>(Wagg);
    gemm1_mma<<<dim3(HEADS, (NTOT + 127) / 128), 256, GSMEM>>>(b1, a1w, a2w);

    // join, then edge aggregation (all heads per warp) + output GEMM
    cudaStreamWaitEvent(0, evCSR, 0);
    edge_agg_kernel<<<(N0C * 3 + 7) / 8, 256>>>(a1b, a2b, nnz0, nnz0 + nnz1);
    gemm2_mma<<<(N0C + 127) / 128, 256, GSMEM>>>(bagg, out);
}

// round 15
// speedup vs baseline: 1.0295x; 1.0295x over previous
#include <cuda_runtime.h>
#include <cuda_bf16.h>
#include <cuda_fp16.h>
#include <math.h>
#include <stdint.h>

#define N0C 30000
#define N1C 90000
#define N2C 60000
#define NTOT (N0C + N1C + N2C)   // 180000
#define DIN  256
#define DOUT 128
#define HEADS 4
#define EMAX 1320000

#define TILEB  8192u             // 128 rows x 32 fp16 (64B) = 8KB
#define STAGEB (3u * TILEB)      // A, Bhi, Blo
#define NSTG   3u
#define GSMEM  (NSTG * STAGEB + 1024u)

// ---------------- scratch (device globals; no runtime allocation) ------------
__device__ __align__(128) __half g_Xf16[(size_t)NTOT * DIN];
__device__ __align__(128) __half g_W1t_hi[HEADS * DOUT * DIN];    // [h][n][k]
__device__ __align__(128) __half g_W1t_lo[HEADS * DOUT * DIN];
__device__ __align__(128) __half g_Waggt_hi[HEADS * DOUT * 512];  // [h][n][k]
__device__ __align__(128) __half g_Waggt_lo[HEADS * DOUT * 512];
__device__ __align__(128) __half g_Yf16[(size_t)NTOT * HEADS * DOUT]; // [row][h][128]
__device__ __align__(128) float  g_a1 [N0C * HEADS];    // [node][h]
__device__ __align__(128) float  g_a2 [NTOT * HEADS];   // [node][h]
__device__ __align__(128) __half g_aggf16[(size_t)HEADS * 3 * N0C * DOUT]; // [h][lvl][row][128]
// CSR scratch
__device__ int g_cnt   [3 * N0C];
__device__ int g_rowptr[3 * (N0C + 1)];
__device__ int g_pos   [3 * N0C];
__device__ int g_ecol  [EMAX];

// ---------------- PTX helpers (all base-ISA) ----------------------------------
__device__ __forceinline__ uint32_t smem_u32(const void* p) {
    uint32_t a;
    asm("{ .reg .u64 t; cvta.to.shared.u64 t, %1; cvt.u32.u64 %0, t; }" : "=r"(a) : "l"(p));
    return a;
}
__device__ __forceinline__ void cpa16(uint32_t dst, const void* src, uint32_t n) {
    asm volatile("cp.async.cg.shared.global [%0], [%1], 16, %2;" :: "r"(dst), "l"(src), "r"(n));
}
__device__ __forceinline__ void cp_commit() { asm volatile("cp.async.commit_group;" ::: "memory"); }
__device__ __forceinline__ void cpwait1()  { asm volatile("cp.async.wait_group 1;" ::: "memory"); }
__device__ __forceinline__ void cpwait0()  { asm volatile("cp.async.wait_group 0;" ::: "memory"); }

__device__ __forceinline__ void ldsm4(uint32_t* r, uint32_t addr) {
    asm volatile("ldmatrix.sync.aligned.m8n8.x4.shared.b16 {%0,%1,%2,%3}, [%4];"
                 : "=r"(r[0]), "=r"(r[1]), "=r"(r[2]), "=r"(r[3]) : "r"(addr));
}
__device__ __forceinline__ void mma16816h(float* c, const uint32_t* a, const uint32_t* b) {
    asm volatile("mma.sync.aligned.m16n8k16.row.col.f32.f16.f16.f32 "
                 "{%0,%1,%2,%3}, {%4,%5,%6,%7}, {%8,%9}, {%0,%1,%2,%3};"
                 : "+f"(c[0]), "+f"(c[1]), "+f"(c[2]), "+f"(c[3])
                 : "r"(a[0]), "r"(a[1]), "r"(a[2]), "r"(a[3]), "r"(b[0]), "r"(b[1]));
}
__device__ __forceinline__ uint32_t swz(uint32_t r, uint32_t c) {
    return r * 64u + ((c ^ ((r >> 1) & 3u)) << 4);
}

// ---------------- pack helpers ------------------------------------------------
__device__ __forceinline__ uint32_t pack2h(__half a, __half b) {
    return (uint32_t)__half_as_ushort(a) | ((uint32_t)__half_as_ushort(b) << 16);
}
__device__ __forceinline__ void split1h(float v, __half& h, __half& l) {
    h = __float2half_rn(v);
    l = __float2half_rn(v - __half2float(h));
}

__global__ __launch_bounds__(256) void pack_x_kernel(
    const float* __restrict__ x0, const float* __restrict__ x1, const float* __restrict__ x2)
{
    size_t i = (size_t)blockIdx.x * 256 + threadIdx.x;   // float4 index
    if (i >= (size_t)NTOT * (DIN / 4)) return;
    int row = (int)(i >> 6);
    int c4  = (int)(i & 63);
    const float* src;
    if (row < N0C)            src = x0 + (size_t)row * DIN;
    else if (row < N0C + N1C) src = x1 + (size_t)(row - N0C) * DIN;
    else                      src = x2 + (size_t)(row - N0C - N1C) * DIN;
    float4 v = reinterpret_cast<const float4*>(src)[c4];
    reinterpret_cast<uint2*>(g_Xf16)[i] = make_uint2(
        pack2h(__float2half_rn(v.x), __float2half_rn(v.y)),
        pack2h(__float2half_rn(v.z), __float2half_rn(v.w)));
}

__global__ __launch_bounds__(256) void split_w1_kernel(const float* __restrict__ W1)
{
    int i = blockIdx.x * 256 + threadIdx.x;              // [h][n][k]
    if (i >= HEADS * DOUT * DIN) return;
    int h = i >> 15, n = (i >> 8) & 127, k = i & 255;
    float v = W1[(size_t)h * DIN * DOUT + (size_t)k * DOUT + n];
    __half hi, lo; split1h(v, hi, lo);
    g_W1t_hi[i] = hi; g_W1t_lo[i] = lo;
}

__global__ __launch_bounds__(256) void split_wagg_kernel(const float* __restrict__ Wagg)
{
    int i = blockIdx.x * 256 + threadIdx.x;              // [h][n][k], k<512
    if (i >= HEADS * DOUT * 512) return;
    int h = i >> 16, n = (i >> 9) & 127, k = i & 511;
    float v = Wagg[(size_t)h * 512 * DOUT + (size_t)k * DOUT + n];
    __half hi, lo; split1h(v, hi, lo);
    g_Waggt_hi[i] = hi; g_Waggt_lo[i] = lo;
}

__global__ __launch_bounds__(256) void zero_small_kernel()
{
    int i = blockIdx.x * 256 + threadIdx.x;
    if (i < N0C * HEADS)  g_a1[i] = 0.f;
    if (i < NTOT * HEADS) g_a2[i] = 0.f;
    if (i < 3 * N0C)      g_cnt[i] = 0;
}

// ---------------- CSR build ----------------------------------------------------
__global__ __launch_bounds__(256) void hist_kernel(const int* __restrict__ rows, int nnz, int lvl)
{
    int i = blockIdx.x * 256 + threadIdx.x;
    if (i < nnz) atomicAdd(&g_cnt[lvl * N0C + rows[i]], 1);
}

__global__ __launch_bounds__(1024) void scan_kernel()   // grid = 3
{
    const int lvl = blockIdx.x;
    const int* cnt = g_cnt + lvl * N0C;
    int* rp  = g_rowptr + lvl * (N0C + 1);
    int* pos = g_pos + lvl * N0C;
    __shared__ int ssum[1024];
    const int CH = (N0C + 1023) / 1024;   // 30
    int t = threadIdx.x;
    int base = t * CH;
    int s = 0;
    for (int k = 0; k < CH; k++) { int idx = base + k; if (idx < N0C) s += cnt[idx]; }
    ssum[t] = s; __syncthreads();
    for (int off = 1; off < 1024; off <<= 1) {
        int v = (t >= off) ? ssum[t - off] : 0;
        __syncthreads();
        ssum[t] += v;
        __syncthreads();
    }
    int run = (t == 0) ? 0 : ssum[t - 1];
    for (int k = 0; k < CH; k++) {
        int idx = base + k;
        if (idx < N0C) { rp[idx] = run; pos[idx] = run; run += cnt[idx]; }
    }
    if (t == 1023) rp[N0C] = run;
}

__global__ __launch_bounds__(256) void scatter_kernel(
    const int* __restrict__ rows, const int* __restrict__ cols,
    int nnz, int lvl, int ebase)
{
    int i = blockIdx.x * 256 + threadIdx.x;
    if (i >= nnz) return;
    int p = atomicAdd(&g_pos[lvl * N0C + rows[i]], 1);
    g_ecol[ebase + p] = cols[i];
}

// ---------------- 2-pass MMA compute core --------------------------------------
__device__ __forceinline__ void compute_stage2(uint32_t s0, int mwarp, int nwarp,
                                               int lane, float c[2][8][4])
{
    uint32_t a[2][2][4];
#pragma unroll
    for (int i = 0; i < 2; i++)
#pragma unroll
        for (int kk = 0; kk < 2; kk++) {
            uint32_t off = swz((uint32_t)(mwarp + i * 16 + (lane & 15)),
                               (uint32_t)(kk * 2 + (lane >> 4)));
            ldsm4(a[i][kk], s0 + off);
        }
#pragma unroll
    for (int j = 0; j < 4; j++) {
        uint32_t nrow = (uint32_t)(nwarp + j * 16 + ((lane >> 4) << 3) + (lane & 7));
        uint32_t csel = (uint32_t)((lane >> 3) & 1);
#pragma unroll
        for (int kk = 0; kk < 2; kk++) {
            uint32_t off = swz(nrow, (uint32_t)(kk * 2) + csel);
            uint32_t bh[4], bl[4];
            ldsm4(bh, s0 + TILEB + off);
            ldsm4(bl, s0 + 2 * TILEB + off);
#pragma unroll
            for (int i = 0; i < 2; i++) {
                mma16816h(c[i][j * 2 + 0], a[i][kk], bh);
                mma16816h(c[i][j * 2 + 1], a[i][kk], bh + 2);
                mma16816h(c[i][j * 2 + 0], a[i][kk], bl);
                mma16816h(c[i][j * 2 + 1], a[i][kk], bl + 2);
            }
        }
    }
}

// ---------------- GEMM1: Y = relu(X@W1[h]+b1[h]) + fused a1/a2 partial dots ----
// grid = (HEADS, tiles); occ 2 CTAs/SM; 3-stage, wait -> ONE sync -> load -> mma.
__global__ __launch_bounds__(256, 2) void gemm1_mma(
    const float* __restrict__ b1, const float* __restrict__ a1w,
    const float* __restrict__ a2w)
{
    extern __shared__ char smem[];
    __shared__ float sBias[128], sA1w[128], sA2w[128];
    uint32_t sb = smem_u32(smem);
    uint32_t tb = (sb + 1023u) & ~1023u;
    const int tid = threadIdx.x, lane = tid & 31, wid = tid >> 5;
    const int h = blockIdx.x, m0 = blockIdx.y * 128;
    const int mwarp = (wid & 3) * 32, nwarp = (wid >> 2) * 64;

    if (tid < 128) {
        sBias[tid] = b1[h * DOUT + tid];
        sA1w[tid]  = a1w[h * DOUT + tid];
        sA2w[tid]  = a2w[h * DOUT + tid];
    }

    float c[2][8][4];
#pragma unroll
    for (int i = 0; i < 2; i++)
#pragma unroll
        for (int j = 0; j < 8; j++)
#pragma unroll
            for (int q = 0; q < 4; q++) c[i][j][q] = 0.f;

    auto load = [&](int stage, int ks) {
        uint32_t s0 = tb + (uint32_t)stage * STAGEB;
        int k0 = ks * 32;
#pragma unroll
        for (int t = 0; t < 2; t++) {
            int idx = tid * 2 + t;
            int r = idx >> 2, cc = idx & 3;
            uint32_t dsw = swz((uint32_t)r, (uint32_t)cc);
            uint32_t n = (m0 + r < NTOT) ? 16u : 0u;
            size_t aoff = (size_t)(m0 + r) * DIN + k0 + cc * 8;
            size_t boff = ((size_t)h * DOUT + r) * DIN + k0 + cc * 8;
            cpa16(s0 + dsw,             g_Xf16   + aoff, n);
            cpa16(s0 + TILEB + dsw,     g_W1t_hi + boff, 16u);
            cpa16(s0 + 2 * TILEB + dsw, g_W1t_lo + boff, 16u);
        }
        cp_commit();
    };

    const int NKS = DIN / 32;   // 8
    load(0, 0);
    load(1, 1);
    for (int ks = 0; ks < NKS; ks++) {
        // own wait for stage ks data, BEFORE the barrier (covers all warps after sync)
        if (ks + 1 < NKS) cpwait1(); else cpwait0();
        __syncthreads();        // stage ks fully loaded; compute(ks-1) done everywhere
        if (ks + 2 < NKS) load((ks + 2) % 3, ks + 2);   // overwrites stage (ks-1)%3: safe
        compute_stage2(tb + (uint32_t)(ks % 3) * STAGEB, mwarp, nwarp, lane, c);
    }

    // epilogue: Yf16 [row][h][128]; fused a1/a2 dots (head-interleaved)
#pragma unroll
    for (int i = 0; i < 2; i++) {
        int r0 = m0 + mwarp + i * 16 + (lane >> 2);
#pragma unroll
        for (int v = 0; v < 2; v++) {
            int row = r0 + v * 8;
            if (row >= NTOT) continue;
            size_t yfb = ((size_t)row * HEADS + h) * DOUT;
            float p1 = 0.f, p2 = 0.f;
#pragma unroll
            for (int j = 0; j < 8; j++) {
                int col = nwarp + j * 8 + (lane & 3) * 2;
                float y0 = fmaxf(c[i][j][v * 2 + 0] + sBias[col], 0.f);
                float y1 = fmaxf(c[i][j][v * 2 + 1] + sBias[col + 1], 0.f);
                p1 = fmaf(y0, sA1w[col], p1); p1 = fmaf(y1, sA1w[col + 1], p1);
                p2 = fmaf(y0, sA2w[col], p2); p2 = fmaf(y1, sA2w[col + 1], p2);
                *reinterpret_cast<uint32_t*>(g_Yf16 + yfb + col) =
                    pack2h(__float2half_rn(y0), __float2half_rn(y1));
            }
            atomicAdd(&g_a2[row * HEADS + h], p2);
            if (row < N0C) atomicAdd(&g_a1[row * HEADS + h], p1);
        }
    }
}

// ---------------- edge aggregation: all 4 heads per warp, 2-edge unroll ---------
__global__ __launch_bounds__(256) void edge_agg_kernel(
    const float* __restrict__ a1b, const float* __restrict__ a2b,
    int ebase1, int ebase2)
{
    int w = blockIdx.x * 8 + (threadIdx.x >> 5);
    if (w >= N0C * 3) return;
    const int lane = threadIdx.x & 31;
    int lvl = w / N0C;
    int row = w - lvl * N0C;

    int coff, eb;
    if (lvl == 0)      { coff = 0;          eb = 0; }
    else if (lvl == 1) { coff = N0C;        eb = ebase1; }
    else               { coff = N0C + N1C;  eb = ebase2; }

    int beg = g_rowptr[lvl * (N0C + 1) + row];
    int end = g_rowptr[lvl * (N0C + 1) + row + 1];

    float4 a1v = *reinterpret_cast<const float4*>(g_a1 + row * HEADS);
    float a1r[4];
#pragma unroll
    for (int h = 0; h < 4; h++)
        a1r[h] = ((const float*)&a1v)[h] + a1b[h] + a2b[h];

    const float* a2t = g_a2 + (size_t)coff * HEADS;
    const __half* yh = g_Yf16 + (size_t)coff * HEADS * DOUT;
    const int* ec = g_ecol + eb;

    float acc[4][4];
#pragma unroll
    for (int h = 0; h < 4; h++)
#pragma unroll
        for (int q = 0; q < 4; q++) acc[h][q] = 0.f;

    int e = beg;
    for (; e + 1 < end; e += 2) {
        int c0 = __ldg(ec + e);
        int c1 = __ldg(ec + e + 1);
        float4 a20 = *reinterpret_cast<const float4*>(a2t + (size_t)c0 * HEADS);
        float4 a21 = *reinterpret_cast<const float4*>(a2t + (size_t)c1 * HEADS);
        uint2 u0[4], u1[4];
#pragma unroll
        for (int h = 0; h < 4; h++) {
            u0[h] = *reinterpret_cast<const uint2*>(yh + ((size_t)c0 * HEADS + h) * DOUT + lane * 4);
            u1[h] = *reinterpret_cast<const uint2*>(yh + ((size_t)c1 * HEADS + h) * DOUT + lane * 4);
        }
#pragma unroll
        for (int h = 0; h < 4; h++) {
            float att0 = __fdividef(1.f, 1.f + __expf(-(a1r[h] + ((const float*)&a20)[h])));
            float att1 = __fdividef(1.f, 1.f + __expf(-(a1r[h] + ((const float*)&a21)[h])));
            float2 f0 = __half22float2(*reinterpret_cast<__half2*>(&u0[h].x));
            float2 f1 = __half22float2(*reinterpret_cast<__half2*>(&u0[h].y));
            float2 g0 = __half22float2(*reinterpret_cast<__half2*>(&u1[h].x));
            float2 g1 = __half22float2(*reinterpret_cast<__half2*>(&u1[h].y));
            acc[h][0] = fmaf(att0, f0.x, acc[h][0]); acc[h][1] = fmaf(att0, f0.y, acc[h][1]);
            acc[h][2] = fmaf(att0, f1.x, acc[h][2]); acc[h][3] = fmaf(att0, f1.y, acc[h][3]);
            acc[h][0] = fmaf(att1, g0.x, acc[h][0]); acc[h][1] = fmaf(att1, g0.y, acc[h][1]);
            acc[h][2] = fmaf(att1, g1.x, acc[h][2]); acc[h][3] = fmaf(att1, g1.y, acc[h][3]);
        }
    }
    if (e < end) {
        int c0 = __ldg(ec + e);
        float4 a20 = *reinterpret_cast<const float4*>(a2t + (size_t)c0 * HEADS);
        uint2 u0[4];
#pragma unroll
        for (int h = 0; h < 4; h++)
            u0[h] = *reinterpret_cast<const uint2*>(yh + ((size_t)c0 * HEADS + h) * DOUT + lane * 4);
#pragma unroll
        for (int h = 0; h < 4; h++) {
            float att0 = __fdividef(1.f, 1.f + __expf(-(a1r[h] + ((const float*)&a20)[h])));
            float2 f0 = __half22float2(*reinterpret_cast<__half2*>(&u0[h].x));
            float2 f1 = __half22float2(*reinterpret_cast<__half2*>(&u0[h].y));
            acc[h][0] = fmaf(att0, f0.x, acc[h][0]); acc[h][1] = fmaf(att0, f0.y, acc[h][1]);
            acc[h][2] = fmaf(att0, f1.x, acc[h][2]); acc[h][3] = fmaf(att0, f1.y, acc[h][3]);
        }
    }

#pragma unroll
    for (int h = 0; h < 4; h++) {
        size_t ob = (((size_t)h * 3 + lvl) * N0C + row) * DOUT + lane * 4;
        *reinterpret_cast<uint2*>(g_aggf16 + ob) = make_uint2(
            pack2h(__float2half_rn(acc[h][0]), __float2half_rn(acc[h][1])),
            pack2h(__float2half_rn(acc[h][2]), __float2half_rn(acc[h][3])));
    }
}

// ---------------- GEMM2: out = mean_h(cat_h @ Wagg[h]) + mean bias --------------
__global__ __launch_bounds__(256, 2) void gemm2_mma(
    const float* __restrict__ bagg, float* __restrict__ out)
{
    extern __shared__ char smem[];
    __shared__ float sBsum[128];
    uint32_t sb = smem_u32(smem);
    uint32_t tb = (sb + 1023u) & ~1023u;
    const int tid = threadIdx.x, lane = tid & 31, wid = tid >> 5;
    const int m0 = blockIdx.x * 128;
    const int mwarp = (wid & 3) * 32, nwarp = (wid >> 2) * 64;

    if (tid < 128)
        sBsum[tid] = bagg[tid] + bagg[128 + tid] + bagg[256 + tid] + bagg[384 + tid];

    float c[2][8][4];
#pragma unroll
    for (int i = 0; i < 2; i++)
#pragma unroll
        for (int j = 0; j < 8; j++)
#pragma unroll
            for (int q = 0; q < 4; q++) c[i][j][q] = 0.f;

    auto load = [&](int stage, int ks) {
        uint32_t s0 = tb + (uint32_t)stage * STAGEB;
        int chunk = ks >> 2, inner = ks & 3;
        int h = chunk >> 2, part = chunk & 3;
        size_t bbase = ((size_t)h * DOUT) * 512 + part * 128;
#pragma unroll
        for (int t = 0; t < 2; t++) {
            int idx = tid * 2 + t;
            int r = idx >> 2, cc = idx & 3;
            uint32_t dsw = swz((uint32_t)r, (uint32_t)cc);
            uint32_t n = (m0 + r < N0C) ? 16u : 0u;
            size_t aoff;
            const __half* asrc;
            if (part == 0) {
                asrc = g_Yf16;
                aoff = ((size_t)(m0 + r) * HEADS + h) * DOUT + inner * 32 + cc * 8;
            } else {
                asrc = g_aggf16;
                aoff = ((size_t)(h * 3 + part - 1) * N0C + m0 + r) * DOUT + inner * 32 + cc * 8;
            }
            size_t boff = bbase + (size_t)r * 512 + inner * 32 + cc * 8;
            cpa16(s0 + dsw,             asrc + aoff, n);
            cpa16(s0 + TILEB + dsw,     g_Waggt_hi + boff, 16u);
            cpa16(s0 + 2 * TILEB + dsw, g_Waggt_lo + boff, 16u);
        }
        cp_commit();
    };

    const int NKS = 64;   // 4 heads * 4 parts * 4 inner
    load(0, 0);
    load(1, 1);
    for (int ks = 0; ks < NKS; ks++) {
        if (ks + 1 < NKS) cpwait1(); else cpwait0();
        __syncthreads();
        if (ks + 2 < NKS) load((ks + 2) % 3, ks + 2);
        compute_stage2(tb + (uint32_t)(ks % 3) * STAGEB, mwarp, nwarp, lane, c);
    }

#pragma unroll
    for (int i = 0; i < 2; i++) {
        int r0 = m0 + mwarp + i * 16 + (lane >> 2);
#pragma unroll
        for (int v = 0; v < 2; v++) {
            int row = r0 + v * 8;
            if (row >= N0C) continue;
            float* dst = out + (size_t)row * DOUT;
#pragma unroll
            for (int j = 0; j < 8; j++) {
                int col = nwarp + j * 8 + (lane & 3) * 2;
                float v0 = 0.25f * (c[i][j][v * 2 + 0] + sBsum[col]);
                float v1 = 0.25f * (c[i][j][v * 2 + 1] + sBsum[col + 1]);
                *reinterpret_cast<float2*>(dst + col) = make_float2(v0, v1);
            }
        }
    }
}

// ---------------- launcher -------------------------------------------------------
extern "C" void kernel_launch(void* const* d_in, const int* in_sizes, int n_in,
                              void* d_out, int out_size)
{
    const float* x0    = (const float*)d_in[0];
    const float* x1    = (const float*)d_in[1];
    const float* x2    = (const float*)d_in[2];
    const int*   rows0 = (const int*)  d_in[3];
    const int*   cols0 = (const int*)  d_in[4];
    const int*   rows1 = (const int*)  d_in[5];
    const int*   cols1 = (const int*)  d_in[6];
    const int*   rows2 = (const int*)  d_in[7];
    const int*   cols2 = (const int*)  d_in[8];
    const float* W1    = (const float*)d_in[9];
    const float* b1    = (const float*)d_in[10];
    const float* a1w   = (const float*)d_in[11];
    const float* a1b   = (const float*)d_in[12];
    const float* a2w   = (const float*)d_in[13];
    const float* a2b   = (const float*)d_in[14];
    const float* Wagg  = (const float*)d_in[15];
    const float* bagg  = (const float*)d_in[16];
    float* out = (float*)d_out;

    const int nnz0 = in_sizes[3];
    const int nnz1 = in_sizes[5];
    const int nnz2 = in_sizes[7];

    static bool init_done = false;
    static cudaStream_t s2;
    static cudaEvent_t evFork, evCSR;
    if (!init_done) {
        cudaFuncSetAttribute(gemm1_mma, cudaFuncAttributeMaxDynamicSharedMemorySize, GSMEM);
        cudaFuncSetAttribute(gemm2_mma, cudaFuncAttributeMaxDynamicSharedMemorySize, GSMEM);
        cudaStreamCreateWithFlags(&s2, cudaStreamNonBlocking);
        cudaEventCreateWithFlags(&evFork, cudaEventDisableTiming);
        cudaEventCreateWithFlags(&evCSR, cudaEventDisableTiming);
        init_done = true;
    }

    // 0) zero (feeds both branches)
    zero_small_kernel<<<(NTOT * HEADS + 255) / 256, 256>>>();

    // fork: CSR build on side stream, concurrent with pack/split/gemm1
    cudaEventRecord(evFork, 0);
    cudaStreamWaitEvent(s2, evFork, 0);
    hist_kernel<<<(nnz0 + 255) / 256, 256, 0, s2>>>(rows0, nnz0, 0);
    hist_kernel<<<(nnz1 + 255) / 256, 256, 0, s2>>>(rows1, nnz1, 1);
    hist_kernel<<<(nnz2 + 255) / 256, 256, 0, s2>>>(rows2, nnz2, 2);
    scan_kernel<<<3, 1024, 0, s2>>>();
    scatter_kernel<<<(nnz0 + 255) / 256, 256, 0, s2>>>(rows0, cols0, nnz0, 0, 0);
    scatter_kernel<<<(nnz1 + 255) / 256, 256, 0, s2>>>(rows1, cols1, nnz1, 1, nnz0);
    scatter_kernel<<<(nnz2 + 255) / 256, 256, 0, s2>>>(rows2, cols2, nnz2, 2, nnz0 + nnz1);
    cudaEventRecord(evCSR, s2);

    // main branch: pack inputs, gemm1 (single launch, all heads)
    pack_x_kernel<<<(NTOT * (DIN / 4) + 255) / 256, 256>>>(x0, x1, x2);
    split_w1_kernel<<<(HEADS * DOUT * DIN + 255) / 256, 256>>>(W1);
    split_wagg_kernel<<<(HEADS * DOUT * 512 + 255) / 256, 256>>>(Wagg);
    gemm1_mma<<<dim3(HEADS, (NTOT + 127) / 128), 256, GSMEM>>>(b1, a1w, a2w);

    // join, then edge aggregation (all heads per warp) + output GEMM
    cudaStreamWaitEvent(0, evCSR, 0);
    edge_agg_kernel<<<(N0C * 3 + 7) / 8, 256>>>(a1b, a2b, nnz0, nnz0 + nnz1);
    gemm2_mma<<<(N0C + 127) / 128, 256, GSMEM>>>(bagg, out);
}

// round 16
// speedup vs baseline: 1.0355x; 1.0058x over previous
#include <cuda_runtime.h>
#include <cuda_bf16.h>
#include <cuda_fp16.h>
#include <math.h>
#include <stdint.h>

#define N0C 30000
#define N1C 90000
#define N2C 60000
#define NTOT (N0C + N1C + N2C)   // 180000
#define DIN  256
#define DOUT 128
#define HEADS 4
#define EMAX 1320000

#define TILEB  8192u             // 128 rows x 32 fp16 (64B) = 8KB
#define STAGEB (3u * TILEB)      // A, Bhi, Blo
#define NSTG   3u
#define GSMEM  (NSTG * STAGEB + 1024u)

#define TILES_ALL ((NTOT + 127) / 128)   // 1407
#define TILES_A   235                    // covers rows [0, 30080) >= N0C

// ---------------- scratch (device globals; no runtime allocation) ------------
__device__ __align__(128) __half g_Xf16[(size_t)NTOT * DIN];
__device__ __align__(128) __half g_W1t_hi[HEADS * DOUT * DIN];    // [h][n][k]
__device__ __align__(128) __half g_W1t_lo[HEADS * DOUT * DIN];
__device__ __align__(128) __half g_Waggt_hi[HEADS * DOUT * 512];  // [h][n][k]
__device__ __align__(128) __half g_Waggt_lo[HEADS * DOUT * 512];
__device__ __align__(128) __half g_Yf16[(size_t)NTOT * HEADS * DOUT]; // [row][h][128]
__device__ __align__(128) float  g_a1 [N0C * HEADS];    // [node][h]
__device__ __align__(128) float  g_a2 [NTOT * HEADS];   // [node][h]
__device__ __align__(128) __half g_aggf16[(size_t)HEADS * 3 * N0C * DOUT]; // [h][lvl][row][128]
// CSR scratch
__device__ int g_cnt   [3 * N0C];
__device__ int g_rowptr[3 * (N0C + 1)];
__device__ int g_pos   [3 * N0C];
__device__ int g_ecol  [EMAX];

// ---------------- PTX helpers (all base-ISA) ----------------------------------
__device__ __forceinline__ uint32_t smem_u32(const void* p) {
    uint32_t a;
    asm("{ .reg .u64 t; cvta.to.shared.u64 t, %1; cvt.u32.u64 %0, t; }" : "=r"(a) : "l"(p));
    return a;
}
__device__ __forceinline__ void cpa16(uint32_t dst, const void* src, uint32_t n) {
    asm volatile("cp.async.cg.shared.global [%0], [%1], 16, %2;" :: "r"(dst), "l"(src), "r"(n));
}
__device__ __forceinline__ void cp_commit() { asm volatile("cp.async.commit_group;" ::: "memory"); }
__device__ __forceinline__ void cpwait1()  { asm volatile("cp.async.wait_group 1;" ::: "memory"); }
__device__ __forceinline__ void cpwait0()  { asm volatile("cp.async.wait_group 0;" ::: "memory"); }

__device__ __forceinline__ void ldsm4(uint32_t* r, uint32_t addr) {
    asm volatile("ldmatrix.sync.aligned.m8n8.x4.shared.b16 {%0,%1,%2,%3}, [%4];"
                 : "=r"(r[0]), "=r"(r[1]), "=r"(r[2]), "=r"(r[3]) : "r"(addr));
}
__device__ __forceinline__ void mma16816h(float* c, const uint32_t* a, const uint32_t* b) {
    asm volatile("mma.sync.aligned.m16n8k16.row.col.f32.f16.f16.f32 "
                 "{%0,%1,%2,%3}, {%4,%5,%6,%7}, {%8,%9}, {%0,%1,%2,%3};"
                 : "+f"(c[0]), "+f"(c[1]), "+f"(c[2]), "+f"(c[3])
                 : "r"(a[0]), "r"(a[1]), "r"(a[2]), "r"(a[3]), "r"(b[0]), "r"(b[1]));
}
__device__ __forceinline__ uint32_t swz(uint32_t r, uint32_t c) {
    return r * 64u + ((c ^ ((r >> 1) & 3u)) << 4);
}

// ---------------- pack helpers ------------------------------------------------
__device__ __forceinline__ uint32_t pack2h(__half a, __half b) {
    return (uint32_t)__half_as_ushort(a) | ((uint32_t)__half_as_ushort(b) << 16);
}
__device__ __forceinline__ void split1h(float v, __half& h, __half& l) {
    h = __float2half_rn(v);
    l = __float2half_rn(v - __half2float(h));
}

__global__ __launch_bounds__(256) void pack_x_kernel(
    const float* __restrict__ x0, const float* __restrict__ x1, const float* __restrict__ x2)
{
    size_t i = (size_t)blockIdx.x * 256 + threadIdx.x;   // float4 index
    if (i >= (size_t)NTOT * (DIN / 4)) return;
    int row = (int)(i >> 6);
    int c4  = (int)(i & 63);
    const float* src;
    if (row < N0C)            src = x0 + (size_t)row * DIN;
    else if (row < N0C + N1C) src = x1 + (size_t)(row - N0C) * DIN;
    else                      src = x2 + (size_t)(row - N0C - N1C) * DIN;
    float4 v = reinterpret_cast<const float4*>(src)[c4];
    reinterpret_cast<uint2*>(g_Xf16)[i] = make_uint2(
        pack2h(__float2half_rn(v.x), __float2half_rn(v.y)),
        pack2h(__float2half_rn(v.z), __float2half_rn(v.w)));
}

__global__ __launch_bounds__(256) void split_w1_kernel(const float* __restrict__ W1)
{
    int i = blockIdx.x * 256 + threadIdx.x;              // [h][n][k]
    if (i >= HEADS * DOUT * DIN) return;
    int h = i >> 15, n = (i >> 8) & 127, k = i & 255;
    float v = W1[(size_t)h * DIN * DOUT + (size_t)k * DOUT + n];
    __half hi, lo; split1h(v, hi, lo);
    g_W1t_hi[i] = hi; g_W1t_lo[i] = lo;
}

__global__ __launch_bounds__(256) void split_wagg_kernel(const float* __restrict__ Wagg)
{
    int i = blockIdx.x * 256 + threadIdx.x;              // [h][n][k], k<512
    if (i >= HEADS * DOUT * 512) return;
    int h = i >> 16, n = (i >> 9) & 127, k = i & 511;
    float v = Wagg[(size_t)h * 512 * DOUT + (size_t)k * DOUT + n];
    __half hi, lo; split1h(v, hi, lo);
    g_Waggt_hi[i] = hi; g_Waggt_lo[i] = lo;
}

__global__ __launch_bounds__(256) void zero_small_kernel()
{
    int i = blockIdx.x * 256 + threadIdx.x;
    if (i < N0C * HEADS)  g_a1[i] = 0.f;
    if (i < NTOT * HEADS) g_a2[i] = 0.f;
    if (i < 3 * N0C)      g_cnt[i] = 0;
}

// ---------------- CSR build ----------------------------------------------------
__global__ __launch_bounds__(256) void hist_kernel(const int* __restrict__ rows, int nnz, int lvl)
{
    int i = blockIdx.x * 256 + threadIdx.x;
    if (i < nnz) atomicAdd(&g_cnt[lvl * N0C + rows[i]], 1);
}

__global__ __launch_bounds__(1024) void scan_kernel()   // grid = 3
{
    const int lvl = blockIdx.x;
    const int* cnt = g_cnt + lvl * N0C;
    int* rp  = g_rowptr + lvl * (N0C + 1);
    int* pos = g_pos + lvl * N0C;
    __shared__ int ssum[1024];
    const int CH = (N0C + 1023) / 1024;   // 30
    int t = threadIdx.x;
    int base = t * CH;
    int s = 0;
    for (int k = 0; k < CH; k++) { int idx = base + k; if (idx < N0C) s += cnt[idx]; }
    ssum[t] = s; __syncthreads();
    for (int off = 1; off < 1024; off <<= 1) {
        int v = (t >= off) ? ssum[t - off] : 0;
        __syncthreads();
        ssum[t] += v;
        __syncthreads();
    }
    int run = (t == 0) ? 0 : ssum[t - 1];
    for (int k = 0; k < CH; k++) {
        int idx = base + k;
        if (idx < N0C) { rp[idx] = run; pos[idx] = run; run += cnt[idx]; }
    }
    if (t == 1023) rp[N0C] = run;
}

__global__ __launch_bounds__(256) void scatter_kernel(
    const int* __restrict__ rows, const int* __restrict__ cols,
    int nnz, int lvl, int ebase)
{
    int i = blockIdx.x * 256 + threadIdx.x;
    if (i >= nnz) return;
    int p = atomicAdd(&g_pos[lvl * N0C + rows[i]], 1);
    g_ecol[ebase + p] = cols[i];
}

// ---------------- 2-pass MMA compute core --------------------------------------
__device__ __forceinline__ void compute_stage2(uint32_t s0, int mwarp, int nwarp,
                                               int lane, float c[2][8][4])
{
    uint32_t a[2][2][4];
#pragma unroll
    for (int i = 0; i < 2; i++)
#pragma unroll
        for (int kk = 0; kk < 2; kk++) {
            uint32_t off = swz((uint32_t)(mwarp + i * 16 + (lane & 15)),
                               (uint32_t)(kk * 2 + (lane >> 4)));
            ldsm4(a[i][kk], s0 + off);
        }
#pragma unroll
    for (int j = 0; j < 4; j++) {
        uint32_t nrow = (uint32_t)(nwarp + j * 16 + ((lane >> 4) << 3) + (lane & 7));
        uint32_t csel = (uint32_t)((lane >> 3) & 1);
#pragma unroll
        for (int kk = 0; kk < 2; kk++) {
            uint32_t off = swz(nrow, (uint32_t)(kk * 2) + csel);
            uint32_t bh[4], bl[4];
            ldsm4(bh, s0 + TILEB + off);
            ldsm4(bl, s0 + 2 * TILEB + off);
#pragma unroll
            for (int i = 0; i < 2; i++) {
                mma16816h(c[i][j * 2 + 0], a[i][kk], bh);
                mma16816h(c[i][j * 2 + 1], a[i][kk], bh + 2);
                mma16816h(c[i][j * 2 + 0], a[i][kk], bl);
                mma16816h(c[i][j * 2 + 1], a[i][kk], bl + 2);
            }
        }
    }
}

// ---------------- GEMM1: Y = relu(X@W1[h]+b1[h]) + fused a1/a2 partial dots ----
// grid = (HEADS, tiles); tileOff selects the row range; occ 2 CTAs/SM.
__global__ __launch_bounds__(256, 2) void gemm1_mma(
    const float* __restrict__ b1, const float* __restrict__ a1w,
    const float* __restrict__ a2w, int tileOff)
{
    extern __shared__ char smem[];
    __shared__ float sBias[128], sA1w[128], sA2w[128];
    uint32_t sb = smem_u32(smem);
    uint32_t tb = (sb + 1023u) & ~1023u;
    const int tid = threadIdx.x, lane = tid & 31, wid = tid >> 5;
    const int h = blockIdx.x, m0 = (blockIdx.y + tileOff) * 128;
    const int mwarp = (wid & 3) * 32, nwarp = (wid >> 2) * 64;

    if (tid < 128) {
        sBias[tid] = b1[h * DOUT + tid];
        sA1w[tid]  = a1w[h * DOUT + tid];
        sA2w[tid]  = a2w[h * DOUT + tid];
    }

    float c[2][8][4];
#pragma unroll
    for (int i = 0; i < 2; i++)
#pragma unroll
        for (int j = 0; j < 8; j++)
#pragma unroll
            for (int q = 0; q < 4; q++) c[i][j][q] = 0.f;

    auto load = [&](int stage, int ks) {
        uint32_t s0 = tb + (uint32_t)stage * STAGEB;
        int k0 = ks * 32;
#pragma unroll
        for (int t = 0; t < 2; t++) {
            int idx = tid * 2 + t;
            int r = idx >> 2, cc = idx & 3;
            uint32_t dsw = swz((uint32_t)r, (uint32_t)cc);
            uint32_t n = (m0 + r < NTOT) ? 16u : 0u;
            size_t aoff = (size_t)(m0 + r) * DIN + k0 + cc * 8;
            size_t boff = ((size_t)h * DOUT + r) * DIN + k0 + cc * 8;
            cpa16(s0 + dsw,             g_Xf16   + aoff, n);
            cpa16(s0 + TILEB + dsw,     g_W1t_hi + boff, 16u);
            cpa16(s0 + 2 * TILEB + dsw, g_W1t_lo + boff, 16u);
        }
        cp_commit();
    };

    const int NKS = DIN / 32;   // 8
    load(0, 0);
    load(1, 1);
    for (int ks = 0; ks < NKS; ks++) {
        if (ks + 1 < NKS) cpwait1(); else cpwait0();
        __syncthreads();
        if (ks + 2 < NKS) load((ks + 2) % 3, ks + 2);
        compute_stage2(tb + (uint32_t)(ks % 3) * STAGEB, mwarp, nwarp, lane, c);
    }

    // epilogue: Yf16 [row][h][128]; fused a1/a2 dots (head-interleaved)
#pragma unroll
    for (int i = 0; i < 2; i++) {
        int r0 = m0 + mwarp + i * 16 + (lane >> 2);
#pragma unroll
        for (int v = 0; v < 2; v++) {
            int row = r0 + v * 8;
            if (row >= NTOT) continue;
            size_t yfb = ((size_t)row * HEADS + h) * DOUT;
            float p1 = 0.f, p2 = 0.f;
#pragma unroll
            for (int j = 0; j < 8; j++) {
                int col = nwarp + j * 8 + (lane & 3) * 2;
                float y0 = fmaxf(c[i][j][v * 2 + 0] + sBias[col], 0.f);
                float y1 = fmaxf(c[i][j][v * 2 + 1] + sBias[col + 1], 0.f);
                p1 = fmaf(y0, sA1w[col], p1); p1 = fmaf(y1, sA1w[col + 1], p1);
                p2 = fmaf(y0, sA2w[col], p2); p2 = fmaf(y1, sA2w[col + 1], p2);
                *reinterpret_cast<uint32_t*>(g_Yf16 + yfb + col) =
                    pack2h(__float2half_rn(y0), __float2half_rn(y1));
            }
            atomicAdd(&g_a2[row * HEADS + h], p2);
            if (row < N0C) atomicAdd(&g_a1[row * HEADS + h], p1);
        }
    }
}

// ---------------- edge aggregation: all 4 heads per warp, 2-edge unroll ---------
// processes levels [lvlBase, lvlBase + nWork/N0C)
__global__ __launch_bounds__(256) void edge_agg_kernel(
    const float* __restrict__ a1b, const float* __restrict__ a2b,
    int ebase1, int ebase2, int lvlBase, int nWork)
{
    int w = blockIdx.x * 8 + (threadIdx.x >> 5);
    if (w >= nWork) return;
    const int lane = threadIdx.x & 31;
    int lvl = lvlBase + w / N0C;
    int row = w % N0C;

    int coff, eb;
    if (lvl == 0)      { coff = 0;          eb = 0; }
    else if (lvl == 1) { coff = N0C;        eb = ebase1; }
    else               { coff = N0C + N1C;  eb = ebase2; }

    int beg = g_rowptr[lvl * (N0C + 1) + row];
    int end = g_rowptr[lvl * (N0C + 1) + row + 1];

    float4 a1v = *reinterpret_cast<const float4*>(g_a1 + row * HEADS);
    float a1r[4];
#pragma unroll
    for (int h = 0; h < 4; h++)
        a1r[h] = ((const float*)&a1v)[h] + a1b[h] + a2b[h];

    const float* a2t = g_a2 + (size_t)coff * HEADS;
    const __half* yh = g_Yf16 + (size_t)coff * HEADS * DOUT;
    const int* ec = g_ecol + eb;

    float acc[4][4];
#pragma unroll
    for (int h = 0; h < 4; h++)
#pragma unroll
        for (int q = 0; q < 4; q++) acc[h][q] = 0.f;

    int e = beg;
    for (; e + 1 < end; e += 2) {
        int c0 = __ldg(ec + e);
        int c1 = __ldg(ec + e + 1);
        float4 a20 = *reinterpret_cast<const float4*>(a2t + (size_t)c0 * HEADS);
        float4 a21 = *reinterpret_cast<const float4*>(a2t + (size_t)c1 * HEADS);
        uint2 u0[4], u1[4];
#pragma unroll
        for (int h = 0; h < 4; h++) {
            u0[h] = *reinterpret_cast<const uint2*>(yh + ((size_t)c0 * HEADS + h) * DOUT + lane * 4);
            u1[h] = *reinterpret_cast<const uint2*>(yh + ((size_t)c1 * HEADS + h) * DOUT + lane * 4);
        }
#pragma unroll
        for (int h = 0; h < 4; h++) {
            float att0 = __fdividef(1.f, 1.f + __expf(-(a1r[h] + ((const float*)&a20)[h])));
            float att1 = __fdividef(1.f, 1.f + __expf(-(a1r[h] + ((const float*)&a21)[h])));
            float2 f0 = __half22float2(*reinterpret_cast<__half2*>(&u0[h].x));
            float2 f1 = __half22float2(*reinterpret_cast<__half2*>(&u0[h].y));
            float2 g0 = __half22float2(*reinterpret_cast<__half2*>(&u1[h].x));
            float2 g1 = __half22float2(*reinterpret_cast<__half2*>(&u1[h].y));
            acc[h][0] = fmaf(att0, f0.x, acc[h][0]); acc[h][1] = fmaf(att0, f0.y, acc[h][1]);
            acc[h][2] = fmaf(att0, f1.x, acc[h][2]); acc[h][3] = fmaf(att0, f1.y, acc[h][3]);
            acc[h][0] = fmaf(att1, g0.x, acc[h][0]); acc[h][1] = fmaf(att1, g0.y, acc[h][1]);
            acc[h][2] = fmaf(att1, g1.x, acc[h][2]); acc[h][3] = fmaf(att1, g1.y, acc[h][3]);
        }
    }
    if (e < end) {
        int c0 = __ldg(ec + e);
        float4 a20 = *reinterpret_cast<const float4*>(a2t + (size_t)c0 * HEADS);
        uint2 u0[4];
#pragma unroll
        for (int h = 0; h < 4; h++)
            u0[h] = *reinterpret_cast<const uint2*>(yh + ((size_t)c0 * HEADS + h) * DOUT + lane * 4);
#pragma unroll
        for (int h = 0; h < 4; h++) {
            float att0 = __fdividef(1.f, 1.f + __expf(-(a1r[h] + ((const float*)&a20)[h])));
            float2 f0 = __half22float2(*reinterpret_cast<__half2*>(&u0[h].x));
            float2 f1 = __half22float2(*reinterpret_cast<__half2*>(&u0[h].y));
            acc[h][0] = fmaf(att0, f0.x, acc[h][0]); acc[h][1] = fmaf(att0, f0.y, acc[h][1]);
            acc[h][2] = fmaf(att0, f1.x, acc[h][2]); acc[h][3] = fmaf(att0, f1.y, acc[h][3]);
        }
    }

#pragma unroll
    for (int h = 0; h < 4; h++) {
        size_t ob = (((size_t)h * 3 + lvl) * N0C + row) * DOUT + lane * 4;
        *reinterpret_cast<uint2*>(g_aggf16 + ob) = make_uint2(
            pack2h(__float2half_rn(acc[h][0]), __float2half_rn(acc[h][1])),
            pack2h(__float2half_rn(acc[h][2]), __float2half_rn(acc[h][3])));
    }
}

// ---------------- GEMM2: out = mean_h(cat_h @ Wagg[h]) + mean bias --------------
__global__ __launch_bounds__(256, 2) void gemm2_mma(
    const float* __restrict__ bagg, float* __restrict__ out)
{
    extern __shared__ char smem[];
    __shared__ float sBsum[128];
    uint32_t sb = smem_u32(smem);
    uint32_t tb = (sb + 1023u) & ~1023u;
    const int tid = threadIdx.x, lane = tid & 31, wid = tid >> 5;
    const int m0 = blockIdx.x * 128;
    const int mwarp = (wid & 3) * 32, nwarp = (wid >> 2) * 64;

    if (tid < 128)
        sBsum[tid] = bagg[tid] + bagg[128 + tid] + bagg[256 + tid] + bagg[384 + tid];

    float c[2][8][4];
#pragma unroll
    for (int i = 0; i < 2; i++)
#pragma unroll
        for (int j = 0; j < 8; j++)
#pragma unroll
            for (int q = 0; q < 4; q++) c[i][j][q] = 0.f;

    auto load = [&](int stage, int ks) {
        uint32_t s0 = tb + (uint32_t)stage * STAGEB;
        int chunk = ks >> 2, inner = ks & 3;
        int h = chunk >> 2, part = chunk & 3;
        size_t bbase = ((size_t)h * DOUT) * 512 + part * 128;
#pragma unroll
        for (int t = 0; t < 2; t++) {
            int idx = tid * 2 + t;
            int r = idx >> 2, cc = idx & 3;
            uint32_t dsw = swz((uint32_t)r, (uint32_t)cc);
            uint32_t n = (m0 + r < N0C) ? 16u : 0u;
            size_t aoff;
            const __half* asrc;
            if (part == 0) {
                asrc = g_Yf16;
                aoff = ((size_t)(m0 + r) * HEADS + h) * DOUT + inner * 32 + cc * 8;
            } else {
                asrc = g_aggf16;
                aoff = ((size_t)(h * 3 + part - 1) * N0C + m0 + r) * DOUT + inner * 32 + cc * 8;
            }
            size_t boff = bbase + (size_t)r * 512 + inner * 32 + cc * 8;
            cpa16(s0 + dsw,             asrc + aoff, n);
            cpa16(s0 + TILEB + dsw,     g_Waggt_hi + boff, 16u);
            cpa16(s0 + 2 * TILEB + dsw, g_Waggt_lo + boff, 16u);
        }
        cp_commit();
    };

    const int NKS = 64;   // 4 heads * 4 parts * 4 inner
    load(0, 0);
    load(1, 1);
    for (int ks = 0; ks < NKS; ks++) {
        if (ks + 1 < NKS) cpwait1(); else cpwait0();
        __syncthreads();
        if (ks + 2 < NKS) load((ks + 2) % 3, ks + 2);
        compute_stage2(tb + (uint32_t)(ks % 3) * STAGEB, mwarp, nwarp, lane, c);
    }

#pragma unroll
    for (int i = 0; i < 2; i++) {
        int r0 = m0 + mwarp + i * 16 + (lane >> 2);
#pragma unroll
        for (int v = 0; v < 2; v++) {
            int row = r0 + v * 8;
            if (row >= N0C) continue;
            float* dst = out + (size_t)row * DOUT;
#pragma unroll
            for (int j = 0; j < 8; j++) {
                int col = nwarp + j * 8 + (lane & 3) * 2;
                float v0 = 0.25f * (c[i][j][v * 2 + 0] + sBsum[col]);
                float v1 = 0.25f * (c[i][j][v * 2 + 1] + sBsum[col + 1]);
                *reinterpret_cast<float2*>(dst + col) = make_float2(v0, v1);
            }
        }
    }
}

// ---------------- launcher -------------------------------------------------------
extern "C" void kernel_launch(void* const* d_in, const int* in_sizes, int n_in,
                              void* d_out, int out_size)
{
    const float* x0    = (const float*)d_in[0];
    const float* x1    = (const float*)d_in[1];
    const float* x2    = (const float*)d_in[2];
    const int*   rows0 = (const int*)  d_in[3];
    const int*   cols0 = (const int*)  d_in[4];
    const int*   rows1 = (const int*)  d_in[5];
    const int*   cols1 = (const int*)  d_in[6];
    const int*   rows2 = (const int*)  d_in[7];
    const int*   cols2 = (const int*)  d_in[8];
    const float* W1    = (const float*)d_in[9];
    const float* b1    = (const float*)d_in[10];
    const float* a1w   = (const float*)d_in[11];
    const float* a1b   = (const float*)d_in[12];
    const float* a2w   = (const float*)d_in[13];
    const float* a2b   = (const float*)d_in[14];
    const float* Wagg  = (const float*)d_in[15];
    const float* bagg  = (const float*)d_in[16];
    float* out = (float*)d_out;

    const int nnz0 = in_sizes[3];
    const int nnz1 = in_sizes[5];
    const int nnz2 = in_sizes[7];

    static bool init_done = false;
    static cudaStream_t s2, s3;
    static cudaEvent_t evFork, evCSR, evA, evE0;
    if (!init_done) {
        cudaFuncSetAttribute(gemm1_mma, cudaFuncAttributeMaxDynamicSharedMemorySize, GSMEM);
        cudaFuncSetAttribute(gemm2_mma, cudaFuncAttributeMaxDynamicSharedMemorySize, GSMEM);
        cudaStreamCreateWithFlags(&s2, cudaStreamNonBlocking);
        cudaStreamCreateWithFlags(&s3, cudaStreamNonBlocking);
        cudaEventCreateWithFlags(&evFork, cudaEventDisableTiming);
        cudaEventCreateWithFlags(&evCSR, cudaEventDisableTiming);
        cudaEventCreateWithFlags(&evA, cudaEventDisableTiming);
        cudaEventCreateWithFlags(&evE0, cudaEventDisableTiming);
        init_done = true;
    }

    // 0) zero (feeds both branches)
    zero_small_kernel<<<(NTOT * HEADS + 255) / 256, 256>>>();

    // fork: CSR build on side stream s2, concurrent with pack/split/gemm1
    cudaEventRecord(evFork, 0);
    cudaStreamWaitEvent(s2, evFork, 0);
    hist_kernel<<<(nnz0 + 255) / 256, 256, 0, s2>>>(rows0, nnz0, 0);
    hist_kernel<<<(nnz1 + 255) / 256, 256, 0, s2>>>(rows1, nnz1, 1);
    hist_kernel<<<(nnz2 + 255) / 256, 256, 0, s2>>>(rows2, nnz2, 2);
    scan_kernel<<<3, 1024, 0, s2>>>();
    scatter_kernel<<<(nnz0 + 255) / 256, 256, 0, s2>>>(rows0, cols0, nnz0, 0, 0);
    scatter_kernel<<<(nnz1 + 255) / 256, 256, 0, s2>>>(rows1, cols1, nnz1, 1, nnz0);
    scatter_kernel<<<(nnz2 + 255) / 256, 256, 0, s2>>>(rows2, cols2, nnz2, 2, nnz0 + nnz1);
    cudaEventRecord(evCSR, s2);

    // main branch: pack inputs, then gemm1 split into A (rows<30080) + B (rest)
    pack_x_kernel<<<(NTOT * (DIN / 4) + 255) / 256, 256>>>(x0, x1, x2);
    split_w1_kernel<<<(HEADS * DOUT * DIN + 255) / 256, 256>>>(W1);
    split_wagg_kernel<<<(HEADS * DOUT * 512 + 255) / 256, 256>>>(Wagg);

    gemm1_mma<<<dim3(HEADS, TILES_A), 256, GSMEM>>>(b1, a1w, a2w, 0);
    cudaEventRecord(evA, 0);
    gemm1_mma<<<dim3(HEADS, TILES_ALL - TILES_A), 256, GSMEM>>>(b1, a1w, a2w, TILES_A);

    // side stream s3: level-0 edge aggregation concurrent with gemm1B
    cudaStreamWaitEvent(s3, evA, 0);
    cudaStreamWaitEvent(s3, evCSR, 0);
    edge_agg_kernel<<<(N0C + 7) / 8, 256, 0, s3>>>(a1b, a2b, nnz0, nnz0 + nnz1, 0, N0C);
    cudaEventRecord(evE0, s3);

    // main: levels 1,2 after gemm1B; then join level-0 and run gemm2
    cudaStreamWaitEvent(0, evCSR, 0);
    edge_agg_kernel<<<(2 * N0C + 7) / 8, 256>>>(a1b, a2b, nnz0, nnz0 + nnz1, 1, 2 * N0C);
    cudaStreamWaitEvent(0, evE0, 0);
    gemm2_mma<<<(N0C + 127) / 128, 256, GSMEM>>>(bagg, out);
}